// round 3
// baseline (speedup 1.0000x reference)
#include <cuda_runtime.h>
#include <cstdint>

#define NB 8
#define NT 4096
#define NDIN 1024
#define NDH 1024
#define MTOT (NB * NT)   // 32768

// Scratch: interleaved (c, v) pairs per [b, t, h]. 256 MB total — static
// device array (allowed; no runtime allocation).
__device__ float g_cv[(size_t)MTOT * NDH * 2];

// ---------------------------------------------------------------------------
// GEMM + transform kernel: computes z_pre = x@Wz^T + bz, h_pre = x@Wh^T + bh
// for a 128x64 output tile (both matrices share the A tile), then applies the
// elementwise transform and writes interleaved (c, v).
// ---------------------------------------------------------------------------
#define BM 128
#define BN 64
#define BK 16
#define NKIT (NDIN / BK)
#define SROW 20   // padded smem row stride (floats)

__device__ __forceinline__ uint32_t f2tf(float f) {
    uint32_t r;
    asm("cvt.rna.tf32.f32 %0, %1;" : "=r"(r) : "f"(f));
    return r;
}

__device__ __forceinline__ void mma_tf32(float* d, const uint32_t* a, const uint32_t* b) {
    asm volatile(
        "mma.sync.aligned.m16n8k8.row.col.f32.tf32.tf32.f32 "
        "{%0,%1,%2,%3}, {%4,%5,%6,%7}, {%8,%9}, {%0,%1,%2,%3};"
        : "+f"(d[0]), "+f"(d[1]), "+f"(d[2]), "+f"(d[3])
        : "r"(a[0]), "r"(a[1]), "r"(a[2]), "r"(a[3]), "r"(b[0]), "r"(b[1]));
}

__device__ __forceinline__ void cpa16(uint32_t saddr, const float* g) {
    asm volatile("cp.async.cg.shared.global [%0], [%1], 16;" :: "r"(saddr), "l"(g));
}
__device__ __forceinline__ void cp_commit() { asm volatile("cp.async.commit_group;"); }
template <int N> __device__ __forceinline__ void cp_wait() {
    asm volatile("cp.async.wait_group %0;" :: "n"(N));
}

// c = sigmoid(-zp) = exp(log_coeffs); v = sigmoid(zp) * g(hp) = exp(log_z + log_h_tilda)
__device__ __forceinline__ void transform(float zp, float hp, float& c, float& v) {
    const float e = __expf(-fabsf(zp));
    const float inv = __fdividef(1.0f, 1.0f + e);
    const float sp = (zp >= 0.0f) ? inv : e * inv;   // sigmoid(zp), stable
    c = (zp >= 0.0f) ? e * inv : inv;                // sigmoid(-zp), stable
    float gh;
    if (hp >= 0.0f) {
        gh = hp + 0.5f;
    } else {
        const float e2 = __expf(hp);                 // hp < 0: no overflow
        gh = __fdividef(e2, 1.0f + e2);              // sigmoid(hp)
    }
    v = sp * gh;
}

__global__ void __launch_bounds__(256, 2)
gemm_transform_kernel(const float* __restrict__ x,
                      const float* __restrict__ Wz, const float* __restrict__ bz,
                      const float* __restrict__ Wh, const float* __restrict__ bh)
{
    __shared__ float sA[2][BM * SROW];
    __shared__ float sBz[2][BN * SROW];
    __shared__ float sBh[2][BN * SROW];

    const int tid  = threadIdx.x;
    const int lane = tid & 31;
    const int warp = tid >> 5;
    const int g    = lane >> 2;  // group id (0..7)
    const int t    = lane & 3;   // thread-in-group (0..3)
    const int wm0  = (warp & 3) * 32;   // 4 warps along M
    const int wn0  = (warp >> 2) * 32;  // 2 warps along N
    const int mBase = blockIdx.x * BM;
    const int nBase = blockIdx.y * BN;

    float accZ[2][4][4];
    float accH[2][4][4];
#pragma unroll
    for (int i = 0; i < 2; i++)
#pragma unroll
        for (int j = 0; j < 4; j++)
#pragma unroll
            for (int e = 0; e < 4; e++) { accZ[i][j][e] = 0.0f; accH[i][j][e] = 0.0f; }

    const uint32_t sA_base  = (uint32_t)__cvta_generic_to_shared(&sA[0][0]);
    const uint32_t sBz_base = (uint32_t)__cvta_generic_to_shared(&sBz[0][0]);
    const uint32_t sBh_base = (uint32_t)__cvta_generic_to_shared(&sBh[0][0]);

    auto load_stage = [&](int kt, int s) {
        const int k0 = kt * BK;
        // A tile: 128 rows x 16 cols = 512 float4, 2 per thread
#pragma unroll
        for (int i = 0; i < 2; i++) {
            const int idx = tid + i * 256;
            const int r = idx >> 2;
            const int c = (idx & 3) * 4;
            cpa16(sA_base + (uint32_t)(s * BM * SROW + r * SROW + c) * 4u,
                  x + (size_t)(mBase + r) * NDIN + k0 + c);
        }
        // B tiles: 64 rows x 16 cols = 256 float4 each, 1 per thread
        {
            const int r = tid >> 2;
            const int c = (tid & 3) * 4;
            cpa16(sBz_base + (uint32_t)(s * BN * SROW + r * SROW + c) * 4u,
                  Wz + (size_t)(nBase + r) * NDIN + k0 + c);
            cpa16(sBh_base + (uint32_t)(s * BN * SROW + r * SROW + c) * 4u,
                  Wh + (size_t)(nBase + r) * NDIN + k0 + c);
        }
    };

    load_stage(0, 0);
    cp_commit();

    for (int kt = 0; kt < NKIT; kt++) {
        const int cur = kt & 1;
        if (kt + 1 < NKIT) {
            load_stage(kt + 1, cur ^ 1);
            cp_commit();
            cp_wait<1>();
        } else {
            cp_wait<0>();
        }
        __syncthreads();

        const float* As  = sA[cur];
        const float* Bzs = sBz[cur];
        const float* Bhs = sBh[cur];
#pragma unroll
        for (int kk = 0; kk < BK; kk += 8) {
            uint32_t af[2][4];
#pragma unroll
            for (int i = 0; i < 2; i++) {
                const int m = wm0 + i * 16 + g;
                af[i][0] = f2tf(As[m * SROW + kk + t]);
                af[i][1] = f2tf(As[(m + 8) * SROW + kk + t]);
                af[i][2] = f2tf(As[m * SROW + kk + t + 4]);
                af[i][3] = f2tf(As[(m + 8) * SROW + kk + t + 4]);
            }
#pragma unroll
            for (int j = 0; j < 4; j++) {
                const int n = wn0 + j * 8 + g;
                uint32_t bfz[2], bfh[2];
                bfz[0] = f2tf(Bzs[n * SROW + kk + t]);
                bfz[1] = f2tf(Bzs[n * SROW + kk + t + 4]);
                bfh[0] = f2tf(Bhs[n * SROW + kk + t]);
                bfh[1] = f2tf(Bhs[n * SROW + kk + t + 4]);
#pragma unroll
                for (int i = 0; i < 2; i++) {
                    mma_tf32(accZ[i][j], af[i], bfz);
                    mma_tf32(accH[i][j], af[i], bfh);
                }
            }
        }
        __syncthreads();
    }

    // Epilogue: bias + transform + store interleaved (c, v) as float4 pairs.
#pragma unroll
    for (int j = 0; j < 4; j++) {
        const int col = nBase + wn0 + j * 8 + 2 * t;   // even
        const float bz0 = bz[col], bz1 = bz[col + 1];
        const float bh0 = bh[col], bh1 = bh[col + 1];
#pragma unroll
        for (int i = 0; i < 2; i++) {
            const int row = mBase + wm0 + i * 16 + g;
            float c0, v0, c1, v1, c2, v2, c3, v3;
            transform(accZ[i][j][0] + bz0, accH[i][j][0] + bh0, c0, v0);
            transform(accZ[i][j][1] + bz1, accH[i][j][1] + bh1, c1, v1);
            transform(accZ[i][j][2] + bz0, accH[i][j][2] + bh0, c2, v2);
            transform(accZ[i][j][3] + bz1, accH[i][j][3] + bh1, c3, v3);
            const size_t o0 = (size_t)row * NDH + col;        // even
            const size_t o1 = (size_t)(row + 8) * NDH + col;  // even
            *(float4*)(g_cv + 2 * o0) = make_float4(c0, v0, c1, v1);
            *(float4*)(g_cv + 2 * o1) = make_float4(c2, v2, c3, v3);
        }
    }
}

// ---------------------------------------------------------------------------
// Scan kernel: h_t = c_t * h_{t-1} + v_t, h_init = g(h_prev).
// CTA = 1024 threads = 32 warps; each warp owns one (b, h) chain; CTA owns 32
// consecutive h channels of one batch. Tiles of 128 timesteps are staged
// through smem (coalesced along h for gmem, conflict-free along t for the
// warp scan). Warp scan composes affine maps (a,b): f∘g = (a_f*a_g, a_f*b_g + b_f).
// ---------------------------------------------------------------------------
__global__ void __launch_bounds__(1024)
scan_kernel(const float* __restrict__ h_prev, float* __restrict__ out)
{
    __shared__ float sc[128][33];
    __shared__ float sv[128][33];

    const int tid   = threadIdx.x;
    const int lane  = tid & 31;
    const int w     = tid >> 5;               // warp = channel within CTA
    const int b     = blockIdx.x >> 5;        // 8 batches
    const int hBase = (blockIdx.x & 31) << 5; // 32 channel-groups of 32

    // h_init = g(h_prev)
    const float hp0 = h_prev[b * NDH + hBase + w];
    float h;
    if (hp0 >= 0.0f) {
        h = hp0 + 0.5f;
    } else {
        const float e = __expf(hp0);
        h = __fdividef(e, 1.0f + e);
    }

    const int lr   = tid >> 3;        // load row (t offset) 0..127
    const int hOff = (tid & 7) * 4;   // 4 channels per thread: 0,4,...,28

    for (int t0 = 0; t0 < NT; t0 += 128) {
        const size_t rowIdx = (size_t)(b * NT + t0 + lr);
        // Interleaved load: two float4 = (c,v) pairs for 4 channels.
        const float* src = g_cv + rowIdx * (NDH * 2) + (size_t)(hBase + hOff) * 2;
        const float4 q0 = *(const float4*)(src);
        const float4 q1 = *(const float4*)(src + 4);
        sc[lr][hOff]     = q0.x; sv[lr][hOff]     = q0.y;
        sc[lr][hOff + 1] = q0.z; sv[lr][hOff + 1] = q0.w;
        sc[lr][hOff + 2] = q1.x; sv[lr][hOff + 2] = q1.y;
        sc[lr][hOff + 3] = q1.z; sv[lr][hOff + 3] = q1.w;
        __syncthreads();

#pragma unroll
        for (int s = 0; s < 4; s++) {
            const int tt = s * 32 + lane;
            float a  = sc[tt][w];
            float bb = sv[tt][w];
#pragma unroll
            for (int d = 1; d < 32; d <<= 1) {
                const float ap = __shfl_up_sync(0xffffffffu, a, d);
                const float bp = __shfl_up_sync(0xffffffffu, bb, d);
                if (lane >= d) {
                    bb = fmaf(a, bp, bb);   // must use pre-update a
                    a *= ap;
                }
            }
            const float hn = fmaf(a, h, bb);  // apply carry
            sc[tt][w] = hn;                   // reuse c-tile as output tile
            h = __shfl_sync(0xffffffffu, hn, 31);
        }
        __syncthreads();

        float4 o;
        o.x = sc[lr][hOff]; o.y = sc[lr][hOff + 1];
        o.z = sc[lr][hOff + 2]; o.w = sc[lr][hOff + 3];
        *(float4*)(out + rowIdx * NDH + hBase + hOff) = o;
        __syncthreads();  // protect smem before next tile's load
    }
}

// ---------------------------------------------------------------------------
extern "C" void kernel_launch(void* const* d_in, const int* in_sizes, int n_in,
                              void* d_out, int out_size)
{
    (void)in_sizes; (void)n_in; (void)out_size;
    const float* x      = (const float*)d_in[0];
    const float* h_prev = (const float*)d_in[1];
    const float* Wz     = (const float*)d_in[2];
    const float* bz     = (const float*)d_in[3];
    const float* Wh     = (const float*)d_in[4];
    const float* bh     = (const float*)d_in[5];
    float* out = (float*)d_out;

    dim3 grid(MTOT / BM, NDH / BN);  // 256 x 16
    gemm_transform_kernel<<<grid, 256>>>(x, Wz, bz, Wh, bh);
    scan_kernel<<<256, 1024>>>(h_prev, out);
}